// round 1
// baseline (speedup 1.0000x reference)
#include <cuda_runtime.h>
#include <cstdint>

// Problem constants (from reference)
#define PCR0      (-51.2f)
#define VX        (0.05f)
#define STRIDE_F  (4.0f)
#define FW        512
#define FH        512
#define NUM_CLASSES 10
#define NUM_MAX_OBJS 500
#define BATCH     16
#define OVERLAP   (0.1f)
#define MIN_RADIUS 2
#define RMAX      16
#define EPS_F32   (1.1920929e-07f)

// Output layout (float32, concatenated in reference-return order)
#define HEAT_ELEMS   ((size_t)BATCH * NUM_CLASSES * FH * FW)   // 41,943,040
#define BOXES_ELEMS  ((size_t)BATCH * NUM_MAX_OBJS * 8)        // 64,000
#define INDS_ELEMS   ((size_t)BATCH * NUM_MAX_OBJS)            // 8,000
#define MASK_ELEMS   ((size_t)BATCH * NUM_MAX_OBJS)            // 8,000

__device__ __forceinline__ float gaussian_radius(float h, float w, float ov) {
    // height = dxf, width = dyf (matches reference arg order)
    float b1 = h + w;
    float c1 = w * h * (1.0f - ov) / (1.0f + ov);
    float sq1 = sqrtf(fmaxf(b1 * b1 - 4.0f * c1, 0.0f));
    float r1 = (b1 + sq1) * 0.5f;

    float b2 = 2.0f * (h + w);
    float c2 = (1.0f - ov) * w * h;
    float sq2 = sqrtf(fmaxf(b2 * b2 - 16.0f * c2, 0.0f));
    float r2 = (b2 + sq2) * 0.5f;

    float a3 = 4.0f * ov;
    float b3 = -2.0f * ov * (h + w);
    float c3 = (ov - 1.0f) * w * h;
    float sq3 = sqrtf(fmaxf(b3 * b3 - 4.0f * a3 * c3, 0.0f));
    float r3 = (b3 + sq3) / (2.0f * a3);

    return fminf(fminf(r1, r2), r3);
}

__global__ void splat_kernel(const float* __restrict__ gt,
                             float* __restrict__ heat,
                             float* __restrict__ boxes,
                             float* __restrict__ inds,
                             float* __restrict__ mask)
{
    const int obj = blockIdx.x;                 // 0 .. BATCH*NUM_MAX_OBJS-1
    const int b   = obj / NUM_MAX_OBJS;

    const float* g = gt + (size_t)obj * 8;
    const float x  = g[0], y  = g[1], z  = g[2];
    const float dx = g[3], dy = g[4], dz = g[5];
    const float hd = g[6];
    const int   cls = (int)(g[7] - 1.0f);

    // coords (replicate reference: two sequential f32 divisions)
    float coord_x = (x - PCR0) / VX / STRIDE_F;
    float coord_y = (y - PCR0) / VX / STRIDE_F;
    coord_x = fminf(fmaxf(coord_x, 0.0f), (float)FW - 0.5f);
    coord_y = fminf(fmaxf(coord_y, 0.0f), (float)FH - 0.5f);
    const int cxi = (int)coord_x;   // truncation == astype(int32) for >=0
    const int cyi = (int)coord_y;

    const float dxf = dx / VX / STRIDE_F;
    const float dyf = dy / VX / STRIDE_F;

    float radf = gaussian_radius(dxf, dyf, OVERLAP);
    int r = (int)radf;                                  // trunc toward zero (positive)
    r = min(max(r, MIN_RADIUS), RMAX);

    const bool valid = (dxf > 0.0f) && (dyf > 0.0f) &&
                       (cxi >= 0) && (cxi <= FW) &&
                       (cyi >= 0) && (cyi <= FH);

    // Per-object scalar outputs (thread 0)
    if (threadIdx.x == 0) {
        const float vf = valid ? 1.0f : 0.0f;
        float* bo = boxes + (size_t)obj * 8;
        bo[0] = (coord_x - (float)cxi) * vf;
        bo[1] = (coord_y - (float)cyi) * vf;
        bo[2] = z * vf;
        bo[3] = logf(fmaxf(dx, 1e-12f)) * vf;
        bo[4] = logf(fmaxf(dy, 1e-12f)) * vf;
        bo[5] = logf(fmaxf(dz, 1e-12f)) * vf;
        bo[6] = cosf(hd) * vf;
        bo[7] = sinf(hd) * vf;
        inds[obj] = valid ? (float)(cyi * FW + cxi) : 0.0f;
        mask[obj] = vf;
    }

    if (!valid) return;

    const int c = min(max(cls, 0), NUM_CLASSES - 1);
    float* plane = heat + ((size_t)(b * NUM_CLASSES + c) * FH) * FW;

    const float sigma   = (2.0f * (float)r + 1.0f) / 6.0f;
    const float inv2s2  = 1.0f / (2.0f * sigma * sigma);

    const int side = 2 * r + 1;
    const int tot  = side * side;

    for (int i = threadIdx.x; i < tot; i += blockDim.x) {
        const int oi = i / side - r;
        const int oj = i % side - r;
        const int yy = cyi + oi;
        const int xx = cxi + oj;
        if (yy < 0 || yy >= FH || xx < 0 || xx >= FW) continue;
        const float d2 = (float)(oi * oi + oj * oj);
        const float gv = expf(-d2 * inv2s2);
        if (gv < EPS_F32) continue;
        // non-negative floats: uint bit ordering == float ordering; buffer zero-init
        atomicMax((unsigned int*)&plane[(size_t)yy * FW + xx], __float_as_uint(gv));
    }
}

extern "C" void kernel_launch(void* const* d_in, const int* in_sizes, int n_in,
                              void* d_out, int out_size) {
    const float* gt = (const float*)d_in[0];
    float* out = (float*)d_out;

    float* heat  = out;
    float* boxes = out + HEAT_ELEMS;
    float* inds  = out + HEAT_ELEMS + BOXES_ELEMS;
    float* mask  = out + HEAT_ELEMS + BOXES_ELEMS + INDS_ELEMS;

    // Zero the full output buffer (heatmap background + invalid-object slots)
    cudaMemsetAsync(d_out, 0, (size_t)out_size * sizeof(float));

    splat_kernel<<<BATCH * NUM_MAX_OBJS, 128>>>(gt, heat, boxes, inds, mask);
}